// round 1
// baseline (speedup 1.0000x reference)
#include <cuda_runtime.h>

#define OUTB 7
#define NCH 256
#define FH 50
#define FW 50
#define NROI 256
#define NEGV (-3e38f)
#define WARPS_PER_BLOCK 8
#define TILE_DIM 20   // Lh, Lw <= 19 given input ranges; clamped defensively

// Normalized roi batch indices (0 or 1), written by prep kernel.
__device__ int g_idx[NROI];

// Detect int64-vs-int32 roi_indices and normalize into g_idx.
// If the buffer is int64 (little-endian), the int32 view is [v0,0,v1,0,...]
// because all values are in {0,1}. For random int32 {0,1} data, "all odd
// words zero" has probability ~2^-128, so this detection is safe.
// Detection reads only the first 256 int32 words (1 KB) = in-bounds for both.
__global__ void prep_idx_kernel(const int* __restrict__ raw) {
    __shared__ int hi_all_zero;
    int t = threadIdx.x;
    if (t == 0) hi_all_zero = 1;
    __syncthreads();
    if (t < NROI / 2 && raw[2 * t + 1] != 0) hi_all_zero = 0;  // benign race: all writers write 0
    __syncthreads();
    if (t < NROI) {
        // int64 case: value r lives at int32 word 2r (buffer is 2 KB, in-bounds).
        g_idx[t] = hi_all_zero ? raw[2 * t] : raw[t];
    }
}

__global__ void __launch_bounds__(WARPS_PER_BLOCK * 32)
roipool_kernel(const float* __restrict__ feat,
               const float* __restrict__ rois,
               float* __restrict__ out) {
    __shared__ float tile[WARPS_PER_BLOCK][TILE_DIM * TILE_DIM];

    const int warp = threadIdx.x >> 5;
    const int lane = threadIdx.x & 31;
    const int idx  = blockIdx.x * WARPS_PER_BLOCK + warp;  // idx = r * NCH + c
    const int r    = idx >> 8;   // / NCH (NCH == 256)
    const int c    = idx & 255;

    const int b = g_idx[r];

    // rois row: [x1, y1, x2, y2]; replicate reference exactly:
    //   ri = int32(roi * (1/16))  (fp32 mul, trunc toward zero; all values >= 0)
    //   h-bounds from x coords, w-bounds from y coords (reference's axis quirk)
    const float4 rv = __ldg(((const float4*)rois) + r);
    int x1 = (int)(rv.x * 0.0625f);
    int y1 = (int)(rv.y * 0.0625f);
    int x2 = (int)(rv.z * 0.0625f);
    int y2 = (int)(rv.w * 0.0625f);

    int Lh = x2 - x1;
    int Lw = y2 - y1;
    // Defensive clamps (input ranges guarantee 3 <= L <= 19, coords in [0,49])
    if (Lh < 0) Lh = 0;
    if (Lw < 0) Lw = 0;
    if (Lh > TILE_DIM) Lh = TILE_DIM;
    if (Lw > TILE_DIM) Lw = TILE_DIM;

    // ---- Load region [x1, x1+Lh) x [y1, y1+Lw) into smem, w-contiguous ----
    const float* fbase = feat + ((size_t)b * NCH + c) * (FH * FW);
    const int n = Lh * Lw;
    for (int i = lane; i < n; i += 32) {
        int hh = i / Lw;           // Lw >= 1 whenever n > 0
        int ww = i - hh * Lw;
        int h = x1 + hh;
        int w = y1 + ww;
        float v = (h >= 0 && h < FH && w >= 0 && w < FW)
                      ? __ldg(fbase + h * FW + w)
                      : NEGV;
        tile[warp][hh * TILE_DIM + ww] = v;
    }
    __syncwarp();

    // ---- 49 bins per warp; lanes 0..31 then 0..16 ----
    float* o = out + (size_t)idx * (OUTB * OUTB);
    #pragma unroll 2
    for (int bin = lane; bin < OUTB * OUTB; bin += 32) {
        int ph = bin / OUTB;
        int pw = bin - ph * OUTB;
        int hs = (ph * Lh) / OUTB;
        int he = ((ph + 1) * Lh + OUTB - 1) / OUTB;
        int ws = (pw * Lw) / OUTB;
        int we = ((pw + 1) * Lw + OUTB - 1) / OUTB;

        float m = NEGV;
        for (int hh = hs; hh < he; hh++) {
            const float* trow = &tile[warp][hh * TILE_DIM];
            for (int ww = ws; ww < we; ww++) {
                m = fmaxf(m, trow[ww]);
            }
        }
        o[bin] = m;
    }
}

extern "C" void kernel_launch(void* const* d_in, const int* in_sizes, int n_in,
                              void* d_out, int out_size) {
    const float* features = (const float*)d_in[0];
    const float* rois     = (const float*)d_in[1];
    const int*   roi_idx  = (const int*)d_in[2];  // width detected at runtime
    float* out = (float*)d_out;

    prep_idx_kernel<<<1, 256>>>(roi_idx);

    const int total_pairs = NROI * NCH;                       // 65536 warps
    const int grid = total_pairs / WARPS_PER_BLOCK;           // 8192 blocks
    roipool_kernel<<<grid, WARPS_PER_BLOCK * 32>>>(features, rois, out);
}

// round 3
// speedup vs baseline: 2.3845x; 2.3845x over previous
#include <cuda_runtime.h>

#define OUTB 7
#define NCH 256
#define FH 50
#define FW 50
#define NROI 256
#define NEGV (-3e38f)
#define WPB 4            // warps per block
#define CPW 4            // channels per warp (float4-interleaved tile)
#define TILE_DIM 20      // Lh, Lw <= 19 for valid inputs; clamped defensively
#define CH_STRIDE (FH * FW)   // 2500 floats between channels

// Normalized roi batch indices (0 or 1), written by prep kernel.
__device__ int g_idx[NROI];

// Detect int64-vs-int32 roi_indices and normalize into g_idx.
// int64 little-endian with values in {0,1} -> all odd int32 words are zero.
// Random int32 {0,1} data being all-zero in odd words has prob ~2^-128.
__global__ void prep_idx_kernel(const int* __restrict__ raw) {
    __shared__ int hi_all_zero;
    int t = threadIdx.x;
    if (t == 0) hi_all_zero = 1;
    __syncthreads();
    if (t < NROI / 2 && raw[2 * t + 1] != 0) hi_all_zero = 0;  // benign race
    __syncthreads();
    if (t < NROI) {
        g_idx[t] = hi_all_zero ? raw[2 * t] : raw[t];
    }
}

__global__ void __launch_bounds__(WPB * 32)
roipool_kernel(const float* __restrict__ feat,
               const float* __restrict__ rois,
               float* __restrict__ out) {
    // One tile per warp, channel-interleaved: tile[pos] = {c0, c0+1, c0+2, c0+3}
    __shared__ float4 tile[WPB][TILE_DIM * TILE_DIM];

    const int warp = threadIdx.x >> 5;
    const int lane = threadIdx.x & 31;
    // 16 channels per block (WPB*CPW) -> 16 blocks per roi
    const int r  = blockIdx.x >> 4;
    const int c0 = ((blockIdx.x & 15) << 4) + (warp << 2);

    const int b = g_idx[r];

    // Reference semantics: ri = int32(roi * (1/16)) (fp32 mul, trunc),
    // h-bounds from x coords, w-bounds from y coords (reference's axis quirk).
    const float4 rv = __ldg(((const float4*)rois) + r);
    int x1 = (int)(rv.x * 0.0625f);
    int y1 = (int)(rv.y * 0.0625f);
    int x2 = (int)(rv.z * 0.0625f);
    int y2 = (int)(rv.w * 0.0625f);
    if (x2 > FH) x2 = FH;            // defensive in-bounds clamps
    if (y2 > FW) y2 = FW;
    int Lh = x2 - x1;
    int Lw = y2 - y1;
    if (Lh < 0) Lh = 0; else if (Lh > TILE_DIM) Lh = TILE_DIM;
    if (Lw < 0) Lw = 0; else if (Lw > TILE_DIM) Lw = TILE_DIM;

    // ---- Load region [x1, x1+Lh) x [y1, y1+Lw) for 4 channels into smem ----
    const float* fb = feat + ((size_t)b * NCH + c0) * CH_STRIDE + x1 * FW + y1;
    const int n   = Lh * Lw;
    const int lwd = (Lw > 0) ? Lw : 1;
    int hh = lane / lwd;                 // one runtime div per thread
    int ww = lane - hh * lwd;
    const int qs = 32 / lwd;             // one more; then incremental updates
    const int rs = 32 - qs * lwd;        // 0 <= rs < lwd
    float4* tw = tile[warp];
    for (int i = lane; i < n; i += 32) {
        const float* p = fb + hh * FW + ww;
        float4 v;
        v.x = __ldg(p);
        v.y = __ldg(p + CH_STRIDE);
        v.z = __ldg(p + 2 * CH_STRIDE);
        v.w = __ldg(p + 3 * CH_STRIDE);
        tw[hh * TILE_DIM + ww] = v;
        hh += qs;
        ww += rs;
        if (ww >= lwd) { ww -= lwd; hh += 1; }
    }
    __syncwarp();   // tile is warp-private; warp-level sync suffices

    // ---- 49 bins, lanes 0..31 then 0..16; each lane produces 4 channels ----
    float* o = out + ((size_t)r * NCH + c0) * (OUTB * OUTB);
    for (int bin = lane; bin < OUTB * OUTB; bin += 32) {
        int ph = bin / OUTB;             // const divisor -> mul.hi
        int pw = bin - ph * OUTB;
        int hs = (ph * Lh) / OUTB;
        int he = ((ph + 1) * Lh + OUTB - 1) / OUTB;
        int ws = (pw * Lw) / OUTB;
        int we = ((pw + 1) * Lw + OUTB - 1) / OUTB;

        float4 m = make_float4(NEGV, NEGV, NEGV, NEGV);
        for (int a = hs; a < he; a++) {
            const float4* trow = tw + a * TILE_DIM;
            for (int w2 = ws; w2 < we; w2++) {
                float4 v = trow[w2];
                m.x = fmaxf(m.x, v.x);
                m.y = fmaxf(m.y, v.y);
                m.z = fmaxf(m.z, v.z);
                m.w = fmaxf(m.w, v.w);
            }
        }
        o[bin]                   = m.x;
        o[bin + OUTB * OUTB]     = m.y;
        o[bin + 2 * OUTB * OUTB] = m.z;
        o[bin + 3 * OUTB * OUTB] = m.w;
    }
}

extern "C" void kernel_launch(void* const* d_in, const int* in_sizes, int n_in,
                              void* d_out, int out_size) {
    const float* features = (const float*)d_in[0];
    const float* rois     = (const float*)d_in[1];
    const int*   roi_idx  = (const int*)d_in[2];  // width detected at runtime
    float* out = (float*)d_out;

    prep_idx_kernel<<<1, 256>>>(roi_idx);

    const int grid = (NROI * NCH) / (WPB * CPW);   // 4096 blocks
    roipool_kernel<<<grid, WPB * 32>>>(features, rois, out);
}